// round 3
// baseline (speedup 1.0000x reference)
#include <cuda_runtime.h>
#include <math.h>

// ---------------- problem constants ----------------
#define BATCH   16
#define CIN     256
#define IMGH    64
#define IMGW    64
#define NPIX    4096          // 64*64
#define HEADS   4
#define DK      16
#define DV      64
#define RKS     7
#define TAPS    49            // 7*7
#define PADR    3

// ---------------- device scratch (globals: allowed) ----------------
__device__ float g_q[BATCH * 64 * NPIX];   // raw q projections [b][ch=h*16+k][p]
__device__ float g_k[BATCH * 16 * NPIX];   // raw k projections [b][k][p]
__device__ float g_v[BATCH * 64 * NPIX];   // raw v projections [b][v][p]
__device__ float g_sq[64], g_bq[64];       // BN fold for q: y = x*s + b
__device__ float g_sv[64], g_bv[64];       // BN fold for v
__device__ float g_lamc[BATCH * 16 * 64];  // lambda_c [b][k][v]

// ======================================================================
// K1: fused projection GEMM. Per batch: Y[144,4096] = W[144,256] * X[256,4096]
// ======================================================================
__global__ __launch_bounds__(256)
void k_proj(const float* __restrict__ x,
            const float* __restrict__ Wq,
            const float* __restrict__ Wk,
            const float* __restrict__ Wv) {
    __shared__ float Xs[16][128];
    __shared__ float Ws[144][17];

    const int b   = blockIdx.y;
    const int p0  = blockIdx.x * 128;
    const int tid = threadIdx.x;
    const int ty  = tid >> 4;
    const int tx  = tid & 15;

    const float* xb = x + (size_t)b * CIN * NPIX;

    float acc[9][8];
#pragma unroll
    for (int i = 0; i < 9; ++i)
#pragma unroll
        for (int j = 0; j < 8; ++j) acc[i][j] = 0.f;

    for (int c0 = 0; c0 < CIN; c0 += 16) {
#pragma unroll
        for (int r = 0; r < 8; ++r) {
            int idx = tid + r * 256;
            int cc  = idx >> 7;
            int pp  = idx & 127;
            Xs[cc][pp] = xb[(size_t)(c0 + cc) * NPIX + p0 + pp];
        }
#pragma unroll
        for (int r = 0; r < 9; ++r) {
            int idx = tid + r * 256;
            int o   = idx >> 4;
            int cc  = idx & 15;
            float w;
            if (o < 64)       w = Wq[o * CIN + c0 + cc];
            else if (o < 80)  w = Wk[(o - 64) * CIN + c0 + cc];
            else              w = Wv[(o - 80) * CIN + c0 + cc];
            Ws[o][cc] = w;
        }
        __syncthreads();

#pragma unroll
        for (int cc = 0; cc < 16; ++cc) {
            float a[9], bb[8];
#pragma unroll
            for (int i = 0; i < 9; ++i) a[i] = Ws[ty + 16 * i][cc];
#pragma unroll
            for (int j = 0; j < 8; ++j) bb[j] = Xs[cc][tx + 16 * j];
#pragma unroll
            for (int i = 0; i < 9; ++i)
#pragma unroll
                for (int j = 0; j < 8; ++j) acc[i][j] += a[i] * bb[j];
        }
        __syncthreads();
    }

#pragma unroll
    for (int i = 0; i < 9; ++i) {
        int o = ty + 16 * i;
        float* dst;
        if (o < 64)      dst = g_q + ((size_t)b * 64 + o) * NPIX;
        else if (o < 80) dst = g_k + ((size_t)b * 16 + (o - 64)) * NPIX;
        else             dst = g_v + ((size_t)b * 64 + (o - 80)) * NPIX;
#pragma unroll
        for (int j = 0; j < 8; ++j) dst[p0 + tx + 16 * j] = acc[i][j];
    }
}

// ======================================================================
// K2: BN statistics -> folded scale/bias. 128 blocks.
// ======================================================================
__global__ __launch_bounds__(256)
void k_bnstats(const float* __restrict__ gamma_q, const float* __restrict__ beta_q,
               const float* __restrict__ gamma_v, const float* __restrict__ beta_v) {
    const int ch  = blockIdx.x;
    const int tid = threadIdx.x;

    const float* src;
    float gamma, beta;
    float *sdst, *bdst;
    if (ch < 64) {
        src = g_q + (size_t)ch * NPIX;
        gamma = gamma_q[ch]; beta = beta_q[ch];
        sdst = &g_sq[ch]; bdst = &g_bq[ch];
    } else {
        int c = ch - 64;
        src = g_v + (size_t)c * NPIX;
        gamma = gamma_v[c]; beta = beta_v[c];
        sdst = &g_sv[c]; bdst = &g_bv[c];
    }

    float s = 0.f, s2 = 0.f;
    for (int b = 0; b < BATCH; ++b) {
        const float* p = src + (size_t)b * 64 * NPIX;
        for (int i = tid; i < NPIX; i += 256) {
            float v = p[i];
            s  += v;
            s2 += v * v;
        }
    }
    __shared__ float ss[256], ss2[256];
    ss[tid] = s; ss2[tid] = s2;
    __syncthreads();
    for (int st = 128; st > 0; st >>= 1) {
        if (tid < st) { ss[tid] += ss[tid + st]; ss2[tid] += ss2[tid + st]; }
        __syncthreads();
    }
    if (tid == 0) {
        const float inv_n = 1.0f / 65536.0f;
        float mean = ss[0] * inv_n;
        float var  = ss2[0] * inv_n - mean * mean;
        float sc   = gamma * rsqrtf(var + 1e-5f);
        *sdst = sc;
        *bdst = beta - mean * sc;
    }
}

// ======================================================================
// K3: softmax over k row + lambda_c, fused. One block per (b, k).
// ======================================================================
__global__ __launch_bounds__(256)
void k_lamc() {
    const int bk  = blockIdx.x;
    const int b   = bk >> 4;
    const int kc  = bk & 15;
    const int tid = threadIdx.x;
    const int lane = tid & 31, wrp = tid >> 5;

    const float* krow = g_k + ((size_t)b * 16 + kc) * NPIX;
    const float* vb   = g_v + (size_t)b * 64 * NPIX;

    __shared__ float red[256];

    float m = -1e30f;
    for (int i = tid; i < NPIX; i += 256) m = fmaxf(m, krow[i]);
    red[tid] = m;
    __syncthreads();
    for (int st = 128; st > 0; st >>= 1) {
        if (tid < st) red[tid] = fmaxf(red[tid], red[tid + st]);
        __syncthreads();
    }
    m = red[0];
    __syncthreads();

    float acc[64];
#pragma unroll
    for (int v = 0; v < 64; ++v) acc[v] = 0.f;
    float z = 0.f;

    for (int i = tid; i < NPIX; i += 256) {
        float w = expf(krow[i] - m);
        z += w;
#pragma unroll
        for (int v = 0; v < 64; ++v) acc[v] += w * vb[(size_t)v * NPIX + i];
    }

    red[tid] = z;
    __syncthreads();
    for (int st = 128; st > 0; st >>= 1) {
        if (tid < st) red[tid] += red[tid + st];
        __syncthreads();
    }
    z = red[0];
    __syncthreads();
    const float invz = 1.0f / z;

    __shared__ float part[64][8];
#pragma unroll
    for (int v = 0; v < 64; ++v) {
        float xv = acc[v];
#pragma unroll
        for (int o = 16; o > 0; o >>= 1) xv += __shfl_down_sync(0xffffffffu, xv, o);
        if (lane == 0) part[v][wrp] = xv;
    }
    __syncthreads();
    if (tid < 64) {
        float sum = 0.f;
#pragma unroll
        for (int i = 0; i < 8; ++i) sum += part[tid][i];
        g_lamc[((size_t)b * 16 + kc) * 64 + tid] = g_sv[tid] * sum * invz + g_bv[tid];
    }
}

// ======================================================================
// K5: final fused output, v-split (2 halves of 32 channels) for 3 CTAs/SM.
// grid = (8, 8, BATCH*2). block = 8x8 pixel tile, 256 thr = 64 pix x 4 vg(8 v).
//   Yc: acc[h][vi] += q_bn[h,k,pix] * lam_c[k, vbase+vi]
//   Yp: loop dy: s[h][tt][pix] = sum_k q_bn * R; acc += s * v_halo
// smem = 56KB -> 3 CTAs/SM (24 warps), regs <= 85.
// ======================================================================
#define VHP2 36   // padded channel pitch (32 v channels + 4)

__global__ __launch_bounds__(256, 3)
void k_final(const float* __restrict__ R, float* __restrict__ out) {
    extern __shared__ float sm[];
    float* q_sm    = sm;                 // [64 ch][64 pix]        4096
    float* vh_sm   = q_sm + 4096;        // [196 hpix][VHP2]       7056
    float* s_sm    = vh_sm + 7056;       // [4h][7 tt][64 pix]     1792
    float* lamc_sm = s_sm + 1792;        // [16 k][32 v]            512
    float* R_sm    = lamc_sm + 512;      // [16 k][49 t]            784

    const int bz  = blockIdx.z;
    const int b   = bz >> 1;
    const int vhf = bz & 1;              // v half: channels vhf*32 .. +31
    const int tx0 = blockIdx.x * 8;
    const int ty0 = blockIdx.y * 8;
    const int tid = threadIdx.x;

    // ---- loads ----
    for (int i = tid; i < 784; i += 256) R_sm[i] = R[i];
    for (int i = tid; i < 512; i += 256) {
        int kk = i >> 5, j = i & 31;
        lamc_sm[i] = g_lamc[(size_t)b * 1024 + kk * 64 + vhf * 32 + j];
    }

    {   // q tile with BN, [ch][pix] (all 64 q channels)
        const float* qb = g_q + (size_t)b * 64 * NPIX;
        for (int idx = tid; idx < 4096; idx += 256) {
            int ch = idx >> 6, lp = idx & 63;
            int ly = lp >> 3,  lx = lp & 7;
            float v = qb[(size_t)ch * NPIX + (ty0 + ly) * IMGW + tx0 + lx];
            q_sm[ch * 64 + lp] = v * g_sq[ch] + g_bq[ch];
        }
    }
    {   // v halo 14x14, 32 channels of this half, BN + zero pad
        const float* vb = g_v + (size_t)b * 64 * NPIX;
        for (int idx = tid; idx < 196 * 32; idx += 256) {
            int ch = idx / 196, hp = idx - ch * 196;
            int gch = vhf * 32 + ch;
            int hy = hp / 14,   hx = hp - hy * 14;
            int gy = ty0 + hy - PADR, gx = tx0 + hx - PADR;
            float v = 0.f;
            if (gy >= 0 && gy < IMGH && gx >= 0 && gx < IMGW)
                v = vb[(size_t)gch * NPIX + gy * IMGW + gx] * g_sv[gch] + g_bv[gch];
            vh_sm[hp * VHP2 + ch] = v;
        }
    }
    __syncthreads();

    const int vg  = tid >> 6;   // v-group 0..3 (8 channels each); also head for s-phase
    const int pix = tid & 63;
    const int py  = pix >> 3, px = pix & 7;

    float acc[4][8];
#pragma unroll
    for (int h = 0; h < 4; ++h)
#pragma unroll
        for (int vi = 0; vi < 8; ++vi) acc[h][vi] = 0.f;

    // ---- Yc term ----
#pragma unroll
    for (int kk = 0; kk < 16; ++kk) {
        float q0 = q_sm[(0 * 16 + kk) * 64 + pix];
        float q1 = q_sm[(1 * 16 + kk) * 64 + pix];
        float q2 = q_sm[(2 * 16 + kk) * 64 + pix];
        float q3 = q_sm[(3 * 16 + kk) * 64 + pix];
        const float* lrow = lamc_sm + kk * 32 + vg * 8;
#pragma unroll
        for (int vi = 0; vi < 8; ++vi) {
            float lv = lrow[vi];
            acc[0][vi] += q0 * lv;
            acc[1][vi] += q1 * lv;
            acc[2][vi] += q2 * lv;
            acc[3][vi] += q3 * lv;
        }
    }

    // ---- Yp term: dy row-groups of the 7x7 stencil ----
    for (int dy = 0; dy < RKS; ++dy) {
        __syncthreads();   // protect s_sm from previous-iteration readers
        {   // s phase: thread computes s[h=vg][tt=0..6][pix]
            float qk[16];
#pragma unroll
            for (int kk = 0; kk < 16; ++kk) qk[kk] = q_sm[(vg * 16 + kk) * 64 + pix];
#pragma unroll
            for (int tt = 0; tt < RKS; ++tt) {
                float s = 0.f;
#pragma unroll
                for (int kk = 0; kk < 16; ++kk) s += qk[kk] * R_sm[kk * TAPS + dy * RKS + tt];
                s_sm[(vg * RKS + tt) * 64 + pix] = s;
            }
        }
        __syncthreads();

#pragma unroll
        for (int dx = 0; dx < RKS; ++dx) {
            const int hp = (py + dy) * 14 + (px + dx);
            const float4* vp = (const float4*)(vh_sm + hp * VHP2 + vg * 8);
            float4 v0 = vp[0], v1 = vp[1];
            float vv[8] = {v0.x, v0.y, v0.z, v0.w, v1.x, v1.y, v1.z, v1.w};
            float sh0 = s_sm[(0 * RKS + dx) * 64 + pix];
            float sh1 = s_sm[(1 * RKS + dx) * 64 + pix];
            float sh2 = s_sm[(2 * RKS + dx) * 64 + pix];
            float sh3 = s_sm[(3 * RKS + dx) * 64 + pix];
#pragma unroll
            for (int vi = 0; vi < 8; ++vi) {
                acc[0][vi] += sh0 * vv[vi];
                acc[1][vi] += sh1 * vv[vi];
                acc[2][vi] += sh2 * vv[vi];
                acc[3][vi] += sh3 * vv[vi];
            }
        }
    }

    // ---- store: out channel = h*64 + vhf*32 + vg*8 + vi ----
    const size_t ob = (size_t)b * 256 * NPIX;
    const int gp = (ty0 + py) * IMGW + tx0 + px;
#pragma unroll
    for (int h = 0; h < 4; ++h)
#pragma unroll
        for (int vi = 0; vi < 8; ++vi)
            out[ob + (size_t)(h * 64 + vhf * 32 + vg * 8 + vi) * NPIX + gp] = acc[h][vi];
}

// ======================================================================
extern "C" void kernel_launch(void* const* d_in, const int* in_sizes, int n_in,
                              void* d_out, int out_size) {
    const float* x       = (const float*)d_in[0];
    const float* Wq      = (const float*)d_in[1];
    const float* Wk      = (const float*)d_in[2];
    const float* Wv      = (const float*)d_in[3];
    const float* gamma_q = (const float*)d_in[4];
    const float* beta_q  = (const float*)d_in[5];
    const float* gamma_v = (const float*)d_in[6];
    const float* beta_v  = (const float*)d_in[7];
    const float* R       = (const float*)d_in[8];
    float* out = (float*)d_out;

    const int smemK5 = (4096 + 7056 + 1792 + 512 + 784) * (int)sizeof(float);
    cudaFuncSetAttribute(k_final, cudaFuncAttributeMaxDynamicSharedMemorySize, smemK5);

    k_proj<<<dim3(NPIX / 128, BATCH), 256>>>(x, Wq, Wk, Wv);
    k_bnstats<<<128, 256>>>(gamma_q, beta_q, gamma_v, beta_v);
    k_lamc<<<BATCH * 16, 256>>>();
    k_final<<<dim3(8, 8, BATCH * 2), 256, smemK5>>>(R, out);
}

// round 4
// speedup vs baseline: 1.3394x; 1.3394x over previous
#include <cuda_runtime.h>
#include <math.h>

// ---------------- problem constants ----------------
#define BATCH   16
#define CIN     256
#define IMGH    64
#define IMGW    64
#define NPIX    4096          // 64*64
#define HEADS   4
#define DK      16
#define DV      64
#define RKS     7
#define TAPS    49            // 7*7
#define PADR    3

// ---------------- device scratch (globals: allowed) ----------------
__device__ float g_q[BATCH * 64 * NPIX];   // raw q projections [b][ch=h*16+k][p]
__device__ float g_k[BATCH * 16 * NPIX];   // raw k projections [b][k][p]
__device__ float g_v[BATCH * 64 * NPIX];   // raw v projections [b][v][p]
__device__ float g_sq[64], g_bq[64];       // BN fold for q: y = x*s + b
__device__ float g_sv[64], g_bv[64];       // BN fold for v
__device__ float g_lamc[BATCH * 16 * 64];  // lambda_c [b][k][v]

// ======================================================================
// K1: fused projection GEMM. Per batch: Y[144,4096] = W[144,256] * X[256,4096]
// ======================================================================
__global__ __launch_bounds__(256)
void k_proj(const float* __restrict__ x,
            const float* __restrict__ Wq,
            const float* __restrict__ Wk,
            const float* __restrict__ Wv) {
    __shared__ float Xs[16][128];
    __shared__ float Ws[144][17];

    const int b   = blockIdx.y;
    const int p0  = blockIdx.x * 128;
    const int tid = threadIdx.x;
    const int ty  = tid >> 4;
    const int tx  = tid & 15;

    const float* xb = x + (size_t)b * CIN * NPIX;

    float acc[9][8];
#pragma unroll
    for (int i = 0; i < 9; ++i)
#pragma unroll
        for (int j = 0; j < 8; ++j) acc[i][j] = 0.f;

    for (int c0 = 0; c0 < CIN; c0 += 16) {
#pragma unroll
        for (int r = 0; r < 8; ++r) {
            int idx = tid + r * 256;
            int cc  = idx >> 7;
            int pp  = idx & 127;
            Xs[cc][pp] = xb[(size_t)(c0 + cc) * NPIX + p0 + pp];
        }
#pragma unroll
        for (int r = 0; r < 9; ++r) {
            int idx = tid + r * 256;
            int o   = idx >> 4;
            int cc  = idx & 15;
            float w;
            if (o < 64)       w = Wq[o * CIN + c0 + cc];
            else if (o < 80)  w = Wk[(o - 64) * CIN + c0 + cc];
            else              w = Wv[(o - 80) * CIN + c0 + cc];
            Ws[o][cc] = w;
        }
        __syncthreads();

#pragma unroll
        for (int cc = 0; cc < 16; ++cc) {
            float a[9], bb[8];
#pragma unroll
            for (int i = 0; i < 9; ++i) a[i] = Ws[ty + 16 * i][cc];
#pragma unroll
            for (int j = 0; j < 8; ++j) bb[j] = Xs[cc][tx + 16 * j];
#pragma unroll
            for (int i = 0; i < 9; ++i)
#pragma unroll
                for (int j = 0; j < 8; ++j) acc[i][j] += a[i] * bb[j];
        }
        __syncthreads();
    }

#pragma unroll
    for (int i = 0; i < 9; ++i) {
        int o = ty + 16 * i;
        float* dst;
        if (o < 64)      dst = g_q + ((size_t)b * 64 + o) * NPIX;
        else if (o < 80) dst = g_k + ((size_t)b * 16 + (o - 64)) * NPIX;
        else             dst = g_v + ((size_t)b * 64 + (o - 80)) * NPIX;
#pragma unroll
        for (int j = 0; j < 8; ++j) dst[p0 + tx + 16 * j] = acc[i][j];
    }
}

// ======================================================================
// K2: BN statistics -> folded scale/bias. 128 blocks.
// ======================================================================
__global__ __launch_bounds__(256)
void k_bnstats(const float* __restrict__ gamma_q, const float* __restrict__ beta_q,
               const float* __restrict__ gamma_v, const float* __restrict__ beta_v) {
    const int ch  = blockIdx.x;
    const int tid = threadIdx.x;

    const float* src;
    float gamma, beta;
    float *sdst, *bdst;
    if (ch < 64) {
        src = g_q + (size_t)ch * NPIX;
        gamma = gamma_q[ch]; beta = beta_q[ch];
        sdst = &g_sq[ch]; bdst = &g_bq[ch];
    } else {
        int c = ch - 64;
        src = g_v + (size_t)c * NPIX;
        gamma = gamma_v[c]; beta = beta_v[c];
        sdst = &g_sv[c]; bdst = &g_bv[c];
    }

    float s = 0.f, s2 = 0.f;
    for (int b = 0; b < BATCH; ++b) {
        const float* p = src + (size_t)b * 64 * NPIX;
        for (int i = tid; i < NPIX; i += 256) {
            float v = p[i];
            s  += v;
            s2 += v * v;
        }
    }
    __shared__ float ss[256], ss2[256];
    ss[tid] = s; ss2[tid] = s2;
    __syncthreads();
    for (int st = 128; st > 0; st >>= 1) {
        if (tid < st) { ss[tid] += ss[tid + st]; ss2[tid] += ss2[tid + st]; }
        __syncthreads();
    }
    if (tid == 0) {
        const float inv_n = 1.0f / 65536.0f;
        float mean = ss[0] * inv_n;
        float var  = ss2[0] * inv_n - mean * mean;
        float sc   = gamma * rsqrtf(var + 1e-5f);
        *sdst = sc;
        *bdst = beta - mean * sc;
    }
}

// ======================================================================
// K3: softmax over k row + lambda_c, fused. One block per (b, k).
// ======================================================================
__global__ __launch_bounds__(256)
void k_lamc() {
    const int bk  = blockIdx.x;
    const int b   = bk >> 4;
    const int kc  = bk & 15;
    const int tid = threadIdx.x;
    const int lane = tid & 31, wrp = tid >> 5;

    const float* krow = g_k + ((size_t)b * 16 + kc) * NPIX;
    const float* vb   = g_v + (size_t)b * 64 * NPIX;

    __shared__ float red[256];

    float m = -1e30f;
    for (int i = tid; i < NPIX; i += 256) m = fmaxf(m, krow[i]);
    red[tid] = m;
    __syncthreads();
    for (int st = 128; st > 0; st >>= 1) {
        if (tid < st) red[tid] = fmaxf(red[tid], red[tid + st]);
        __syncthreads();
    }
    m = red[0];
    __syncthreads();

    float acc[64];
#pragma unroll
    for (int v = 0; v < 64; ++v) acc[v] = 0.f;
    float z = 0.f;

    for (int i = tid; i < NPIX; i += 256) {
        float w = expf(krow[i] - m);
        z += w;
#pragma unroll
        for (int v = 0; v < 64; ++v) acc[v] += w * vb[(size_t)v * NPIX + i];
    }

    red[tid] = z;
    __syncthreads();
    for (int st = 128; st > 0; st >>= 1) {
        if (tid < st) red[tid] += red[tid + st];
        __syncthreads();
    }
    z = red[0];
    __syncthreads();
    const float invz = 1.0f / z;

    __shared__ float part[64][8];
#pragma unroll
    for (int v = 0; v < 64; ++v) {
        float xv = acc[v];
#pragma unroll
        for (int o = 16; o > 0; o >>= 1) xv += __shfl_down_sync(0xffffffffu, xv, o);
        if (lane == 0) part[v][wrp] = xv;
    }
    __syncthreads();
    if (tid < 64) {
        float sum = 0.f;
#pragma unroll
        for (int i = 0; i < 8; ++i) sum += part[tid][i];
        g_lamc[((size_t)b * 16 + kc) * 64 + tid] = g_sv[tid] * sum * invz + g_bv[tid];
    }
}

// ======================================================================
// K5: final fused output (vectorized smem paths, 2 CTAs/SM).
//   q_sm  : [64 pix][QP=68 ch]      -> float4 q loads (lane stride 17 f4, cf)
//   s_sm  : [64 pix][tt*4 + h]      -> 1 LDS.128 per tap (lane stride 7 f4, cf)
//   vh_sm : [196 hpix][VHPITCH ch]  -> float4 v loads (stride 17 f4, cf)
// block = 8x8 pixel tile; 256 threads = 64 pixels x 4 v-groups (16 v each).
// ======================================================================
#define VHPITCH 68
#define QP      68
#define SP      28   // s pitch per pixel: 7 tt * 4 heads

__global__ __launch_bounds__(256, 2)
void k_final(const float* __restrict__ R, float* __restrict__ out) {
    extern __shared__ float sm[];
    float* q_sm    = sm;                     // [64 pix][QP]             4352
    float* vh_sm   = q_sm + 64 * QP;         // [196 hpix][VHPITCH]     13328
    float* s_sm    = vh_sm + 196 * VHPITCH;  // [64 pix][SP]             1792
    float* lamc_sm = s_sm + 64 * SP;         // [16 k][64 v]             1024
    float* R_sm    = lamc_sm + 1024;         // [16 k][49 t]              784

    const int b   = blockIdx.z;
    const int tx0 = blockIdx.x * 8;
    const int ty0 = blockIdx.y * 8;
    const int tid = threadIdx.x;

    // ---- loads ----
    for (int i = tid; i < 784; i += 256)  R_sm[i]    = R[i];
    for (int i = tid; i < 1024; i += 256) lamc_sm[i] = g_lamc[(size_t)b * 1024 + i];

    {   // q tile with BN, transposed [pix][ch]
        const float* qb = g_q + (size_t)b * 64 * NPIX;
        for (int idx = tid; idx < 4096; idx += 256) {
            int ch = idx >> 6, lp = idx & 63;
            int ly = lp >> 3,  lx = lp & 7;
            float v = qb[(size_t)ch * NPIX + (ty0 + ly) * IMGW + tx0 + lx];
            q_sm[lp * QP + ch] = v * g_sq[ch] + g_bq[ch];
        }
    }
    {   // v halo 14x14 with BN + zero pad, [hpix][ch]
        const float* vb = g_v + (size_t)b * 64 * NPIX;
        for (int idx = tid; idx < 196 * 64; idx += 256) {
            int ch = idx / 196, hp = idx - ch * 196;
            int hy = hp / 14,   hx = hp - hy * 14;
            int gy = ty0 + hy - PADR, gx = tx0 + hx - PADR;
            float v = 0.f;
            if (gy >= 0 && gy < IMGH && gx >= 0 && gx < IMGW)
                v = vb[(size_t)ch * NPIX + gy * IMGW + gx] * g_sv[ch] + g_bv[ch];
            vh_sm[hp * VHPITCH + ch] = v;
        }
    }
    __syncthreads();

    const int vg  = tid >> 6;   // v-group 0..3 (16 channels each); also head for s-phase
    const int pix = tid & 63;
    const int py  = pix >> 3, px = pix & 7;
    const float* qrow = q_sm + pix * QP;

    float acc[4][16];
#pragma unroll
    for (int h = 0; h < 4; ++h)
#pragma unroll
        for (int vi = 0; vi < 16; ++vi) acc[h][vi] = 0.f;

    // ---- Yc term: kk in chunks of 4, vectorized q + lamc loads ----
#pragma unroll
    for (int kk0 = 0; kk0 < 16; kk0 += 4) {
        float4 qh[4];
#pragma unroll
        for (int h = 0; h < 4; ++h)
            qh[h] = *(const float4*)(qrow + h * 16 + kk0);
#pragma unroll
        for (int j = 0; j < 4; ++j) {
            const float* lrow = lamc_sm + (kk0 + j) * 64 + vg * 16;
            float4 l0 = ((const float4*)lrow)[0];
            float4 l1 = ((const float4*)lrow)[1];
            float4 l2 = ((const float4*)lrow)[2];
            float4 l3 = ((const float4*)lrow)[3];
            float lv[16] = {l0.x, l0.y, l0.z, l0.w, l1.x, l1.y, l1.z, l1.w,
                            l2.x, l2.y, l2.z, l2.w, l3.x, l3.y, l3.z, l3.w};
            float q0 = (j == 0) ? qh[0].x : (j == 1) ? qh[0].y : (j == 2) ? qh[0].z : qh[0].w;
            float q1 = (j == 0) ? qh[1].x : (j == 1) ? qh[1].y : (j == 2) ? qh[1].z : qh[1].w;
            float q2 = (j == 0) ? qh[2].x : (j == 1) ? qh[2].y : (j == 2) ? qh[2].z : qh[2].w;
            float q3 = (j == 0) ? qh[3].x : (j == 1) ? qh[3].y : (j == 2) ? qh[3].z : qh[3].w;
#pragma unroll
            for (int vi = 0; vi < 16; ++vi) {
                acc[0][vi] += q0 * lv[vi];
                acc[1][vi] += q1 * lv[vi];
                acc[2][vi] += q2 * lv[vi];
                acc[3][vi] += q3 * lv[vi];
            }
        }
    }

    // ---- hoist this thread's q (head = vg) for the s-phase ----
    float qk[16];
#pragma unroll
    for (int i4 = 0; i4 < 4; ++i4) {
        float4 t = *(const float4*)(qrow + vg * 16 + i4 * 4);
        qk[i4 * 4 + 0] = t.x; qk[i4 * 4 + 1] = t.y;
        qk[i4 * 4 + 2] = t.z; qk[i4 * 4 + 3] = t.w;
    }

    // ---- Yp term: dy row-groups of the 7x7 stencil ----
    float* srow = s_sm + pix * SP;
    for (int dy = 0; dy < RKS; ++dy) {
        __syncthreads();   // protect s_sm writers from previous-iteration readers
        // s phase: thread computes s[h=vg][tt=0..6] for its pixel
#pragma unroll
        for (int tt = 0; tt < RKS; ++tt) {
            float s = 0.f;
#pragma unroll
            for (int kk = 0; kk < 16; ++kk) s += qk[kk] * R_sm[kk * TAPS + dy * RKS + tt];
            srow[tt * 4 + vg] = s;
        }
        __syncthreads();

#pragma unroll
        for (int dx = 0; dx < RKS; ++dx) {
            const int hp = (py + dy) * 14 + (px + dx);
            const float4* vp = (const float4*)(vh_sm + hp * VHPITCH + vg * 16);
            float4 v0 = vp[0], v1 = vp[1], v2 = vp[2], v3 = vp[3];
            float vv[16] = {v0.x, v0.y, v0.z, v0.w,
                            v1.x, v1.y, v1.z, v1.w,
                            v2.x, v2.y, v2.z, v2.w,
                            v3.x, v3.y, v3.z, v3.w};
            float4 s4 = *(const float4*)(srow + dx * 4);   // h0..h3
#pragma unroll
            for (int vi = 0; vi < 16; ++vi) {
                acc[0][vi] += s4.x * vv[vi];
                acc[1][vi] += s4.y * vv[vi];
                acc[2][vi] += s4.z * vv[vi];
                acc[3][vi] += s4.w * vv[vi];
            }
        }
    }

    // ---- store: out channel = h*64 + v ----
    const size_t ob = (size_t)b * 256 * NPIX;
    const int gp = (ty0 + py) * IMGW + tx0 + px;
#pragma unroll
    for (int h = 0; h < 4; ++h)
#pragma unroll
        for (int vi = 0; vi < 16; ++vi)
            out[ob + (size_t)(h * 64 + vg * 16 + vi) * NPIX + gp] = acc[h][vi];
}

// ======================================================================
extern "C" void kernel_launch(void* const* d_in, const int* in_sizes, int n_in,
                              void* d_out, int out_size) {
    const float* x       = (const float*)d_in[0];
    const float* Wq      = (const float*)d_in[1];
    const float* Wk      = (const float*)d_in[2];
    const float* Wv      = (const float*)d_in[3];
    const float* gamma_q = (const float*)d_in[4];
    const float* beta_q  = (const float*)d_in[5];
    const float* gamma_v = (const float*)d_in[6];
    const float* beta_v  = (const float*)d_in[7];
    const float* R       = (const float*)d_in[8];
    float* out = (float*)d_out;

    const int smemK5 = (64 * QP + 196 * VHPITCH + 64 * SP + 1024 + 784) * (int)sizeof(float);
    cudaFuncSetAttribute(k_final, cudaFuncAttributeMaxDynamicSharedMemorySize, smemK5);

    k_proj<<<dim3(NPIX / 128, BATCH), 256>>>(x, Wq, Wk, Wv);
    k_bnstats<<<128, 256>>>(gamma_q, beta_q, gamma_v, beta_v);
    k_lamc<<<BATCH * 16, 256>>>();
    k_final<<<dim3(8, 8, BATCH), 256, smemK5>>>(R, out);
}

// round 5
// speedup vs baseline: 1.3601x; 1.0155x over previous
#include <cuda_runtime.h>
#include <math.h>

// ---------------- problem constants ----------------
#define BATCH   16
#define CIN     256
#define IMGH    64
#define IMGW    64
#define NPIX    4096          // 64*64
#define HEADS   4
#define DK      16
#define DV      64
#define RKS     7
#define TAPS    49            // 7*7
#define PADR    3

// ---------------- device scratch (globals: allowed) ----------------
__device__ float g_q[BATCH * 64 * NPIX];   // raw q projections [b][ch=h*16+k][p]
__device__ float g_k[BATCH * 16 * NPIX];   // raw k projections [b][k][p]
__device__ float g_v[BATCH * 64 * NPIX];   // raw v projections [b][v][p]
__device__ float g_sq[64], g_bq[64];       // BN fold for q: y = x*s + b
__device__ float g_sv[64], g_bv[64];       // BN fold for v
__device__ float g_lamc[BATCH * 16 * 64];  // lambda_c [b][k][v]

// ======================================================================
// K1: fused projection GEMM. Per batch: Y[144,4096] = W[144,256] * X[256,4096]
// ======================================================================
__global__ __launch_bounds__(256)
void k_proj(const float* __restrict__ x,
            const float* __restrict__ Wq,
            const float* __restrict__ Wk,
            const float* __restrict__ Wv) {
    __shared__ float Xs[16][128];
    __shared__ float Ws[144][17];

    const int b   = blockIdx.y;
    const int p0  = blockIdx.x * 128;
    const int tid = threadIdx.x;
    const int ty  = tid >> 4;
    const int tx  = tid & 15;

    const float* xb = x + (size_t)b * CIN * NPIX;

    float acc[9][8];
#pragma unroll
    for (int i = 0; i < 9; ++i)
#pragma unroll
        for (int j = 0; j < 8; ++j) acc[i][j] = 0.f;

    for (int c0 = 0; c0 < CIN; c0 += 16) {
#pragma unroll
        for (int r = 0; r < 8; ++r) {
            int idx = tid + r * 256;
            int cc  = idx >> 7;
            int pp  = idx & 127;
            Xs[cc][pp] = xb[(size_t)(c0 + cc) * NPIX + p0 + pp];
        }
#pragma unroll
        for (int r = 0; r < 9; ++r) {
            int idx = tid + r * 256;
            int o   = idx >> 4;
            int cc  = idx & 15;
            float w;
            if (o < 64)       w = Wq[o * CIN + c0 + cc];
            else if (o < 80)  w = Wk[(o - 64) * CIN + c0 + cc];
            else              w = Wv[(o - 80) * CIN + c0 + cc];
            Ws[o][cc] = w;
        }
        __syncthreads();

#pragma unroll
        for (int cc = 0; cc < 16; ++cc) {
            float a[9], bb[8];
#pragma unroll
            for (int i = 0; i < 9; ++i) a[i] = Ws[ty + 16 * i][cc];
#pragma unroll
            for (int j = 0; j < 8; ++j) bb[j] = Xs[cc][tx + 16 * j];
#pragma unroll
            for (int i = 0; i < 9; ++i)
#pragma unroll
                for (int j = 0; j < 8; ++j) acc[i][j] += a[i] * bb[j];
        }
        __syncthreads();
    }

#pragma unroll
    for (int i = 0; i < 9; ++i) {
        int o = ty + 16 * i;
        float* dst;
        if (o < 64)      dst = g_q + ((size_t)b * 64 + o) * NPIX;
        else if (o < 80) dst = g_k + ((size_t)b * 16 + (o - 64)) * NPIX;
        else             dst = g_v + ((size_t)b * 64 + (o - 80)) * NPIX;
#pragma unroll
        for (int j = 0; j < 8; ++j) dst[p0 + tx + 16 * j] = acc[i][j];
    }
}

// ======================================================================
// K2: BN statistics -> folded scale/bias. 128 blocks.
// ======================================================================
__global__ __launch_bounds__(256)
void k_bnstats(const float* __restrict__ gamma_q, const float* __restrict__ beta_q,
               const float* __restrict__ gamma_v, const float* __restrict__ beta_v) {
    const int ch  = blockIdx.x;
    const int tid = threadIdx.x;

    const float* src;
    float gamma, beta;
    float *sdst, *bdst;
    if (ch < 64) {
        src = g_q + (size_t)ch * NPIX;
        gamma = gamma_q[ch]; beta = beta_q[ch];
        sdst = &g_sq[ch]; bdst = &g_bq[ch];
    } else {
        int c = ch - 64;
        src = g_v + (size_t)c * NPIX;
        gamma = gamma_v[c]; beta = beta_v[c];
        sdst = &g_sv[c]; bdst = &g_bv[c];
    }

    float s = 0.f, s2 = 0.f;
    for (int b = 0; b < BATCH; ++b) {
        const float* p = src + (size_t)b * 64 * NPIX;
        for (int i = tid; i < NPIX; i += 256) {
            float v = p[i];
            s  += v;
            s2 += v * v;
        }
    }
    __shared__ float ss[256], ss2[256];
    ss[tid] = s; ss2[tid] = s2;
    __syncthreads();
    for (int st = 128; st > 0; st >>= 1) {
        if (tid < st) { ss[tid] += ss[tid + st]; ss2[tid] += ss2[tid + st]; }
        __syncthreads();
    }
    if (tid == 0) {
        const float inv_n = 1.0f / 65536.0f;
        float mean = ss[0] * inv_n;
        float var  = ss2[0] * inv_n - mean * mean;
        float sc   = gamma * rsqrtf(var + 1e-5f);
        *sdst = sc;
        *bdst = beta - mean * sc;
    }
}

// ======================================================================
// K3: softmax over k row + lambda_c, fused. One block per (b, k).
// ======================================================================
__global__ __launch_bounds__(256)
void k_lamc() {
    const int bk  = blockIdx.x;
    const int b   = bk >> 4;
    const int kc  = bk & 15;
    const int tid = threadIdx.x;
    const int lane = tid & 31, wrp = tid >> 5;

    const float* krow = g_k + ((size_t)b * 16 + kc) * NPIX;
    const float* vb   = g_v + (size_t)b * 64 * NPIX;

    __shared__ float red[256];

    float m = -1e30f;
    for (int i = tid; i < NPIX; i += 256) m = fmaxf(m, krow[i]);
    red[tid] = m;
    __syncthreads();
    for (int st = 128; st > 0; st >>= 1) {
        if (tid < st) red[tid] = fmaxf(red[tid], red[tid + st]);
        __syncthreads();
    }
    m = red[0];
    __syncthreads();

    float acc[64];
#pragma unroll
    for (int v = 0; v < 64; ++v) acc[v] = 0.f;
    float z = 0.f;

    for (int i = tid; i < NPIX; i += 256) {
        float w = expf(krow[i] - m);
        z += w;
#pragma unroll
        for (int v = 0; v < 64; ++v) acc[v] += w * vb[(size_t)v * NPIX + i];
    }

    red[tid] = z;
    __syncthreads();
    for (int st = 128; st > 0; st >>= 1) {
        if (tid < st) red[tid] += red[tid + st];
        __syncthreads();
    }
    z = red[0];
    __syncthreads();
    const float invz = 1.0f / z;

    __shared__ float part[64][8];
#pragma unroll
    for (int v = 0; v < 64; ++v) {
        float xv = acc[v];
#pragma unroll
        for (int o = 16; o > 0; o >>= 1) xv += __shfl_down_sync(0xffffffffu, xv, o);
        if (lane == 0) part[v][wrp] = xv;
    }
    __syncthreads();
    if (tid < 64) {
        float sum = 0.f;
#pragma unroll
        for (int i = 0; i < 8; ++i) sum += part[tid][i];
        g_lamc[((size_t)b * 16 + kc) * 64 + tid] = g_sv[tid] * sum * invz + g_bv[tid];
    }
}

// ======================================================================
// K5: final fused output. 512 threads = 64 pix x 8 groups.
// group g: vg2 = g&3 -> v channels vg2*16..+15 ; hh = g>>2 -> heads {2hh,2hh+1}
// per-thread acc[2][16] = 32 regs -> launch_bounds(512,2), 32 warps/SM.
// s-phase: group computes head hs=g&3, tt-range (g>>2 ? 4..6 : 0..3).
// ======================================================================
#define VHPITCH 68
#define QP      68
#define SP      28   // s pitch per pixel: 7 tt * 4 heads

__global__ __launch_bounds__(512, 2)
void k_final(const float* __restrict__ R, float* __restrict__ out) {
    extern __shared__ float sm[];
    float* q_sm    = sm;                     // [64 pix][QP]             4352
    float* vh_sm   = q_sm + 64 * QP;         // [196 hpix][VHPITCH]     13328
    float* s_sm    = vh_sm + 196 * VHPITCH;  // [64 pix][SP]             1792
    float* lamc_sm = s_sm + 64 * SP;         // [16 k][64 v]             1024
    float* R_sm    = lamc_sm + 1024;         // [16 k][49 t]              784

    const int b   = blockIdx.z;
    const int tx0 = blockIdx.x * 8;
    const int ty0 = blockIdx.y * 8;
    const int tid = threadIdx.x;

    // ---- loads (512 threads) ----
    for (int i = tid; i < 784; i += 512)  R_sm[i]    = R[i];
    for (int i = tid; i < 1024; i += 512) lamc_sm[i] = g_lamc[(size_t)b * 1024 + i];

    {   // q tile with BN, transposed [pix][ch]
        const float* qb = g_q + (size_t)b * 64 * NPIX;
        for (int idx = tid; idx < 4096; idx += 512) {
            int ch = idx >> 6, lp = idx & 63;
            int ly = lp >> 3,  lx = lp & 7;
            float v = qb[(size_t)ch * NPIX + (ty0 + ly) * IMGW + tx0 + lx];
            q_sm[lp * QP + ch] = v * g_sq[ch] + g_bq[ch];
        }
    }
    {   // v halo 14x14 with BN + zero pad, [hpix][ch]
        const float* vb = g_v + (size_t)b * 64 * NPIX;
        for (int idx = tid; idx < 196 * 64; idx += 512) {
            int ch = idx / 196, hp = idx - ch * 196;
            int hy = hp / 14,   hx = hp - hy * 14;
            int gy = ty0 + hy - PADR, gx = tx0 + hx - PADR;
            float v = 0.f;
            if (gy >= 0 && gy < IMGH && gx >= 0 && gx < IMGW)
                v = vb[(size_t)ch * NPIX + gy * IMGW + gx] * g_sv[ch] + g_bv[ch];
            vh_sm[hp * VHPITCH + ch] = v;
        }
    }
    __syncthreads();

    const int g   = tid >> 6;        // group 0..7
    const int pix = tid & 63;
    const int vg2 = g & 3;           // v channels vg2*16..+15
    const int hh  = g >> 2;          // heads 2hh, 2hh+1
    const int py  = pix >> 3, px = pix & 7;
    const float* qrow = q_sm + pix * QP;
    float* srow = s_sm + pix * SP;

    float acc[2][16];
#pragma unroll
    for (int h = 0; h < 2; ++h)
#pragma unroll
        for (int vi = 0; vi < 16; ++vi) acc[h][vi] = 0.f;

    // ---- Yc term (heads 2hh, 2hh+1) ----
#pragma unroll
    for (int kk0 = 0; kk0 < 16; kk0 += 4) {
        float4 q0v = *(const float4*)(qrow + (2 * hh + 0) * 16 + kk0);
        float4 q1v = *(const float4*)(qrow + (2 * hh + 1) * 16 + kk0);
        float q0a[4] = {q0v.x, q0v.y, q0v.z, q0v.w};
        float q1a[4] = {q1v.x, q1v.y, q1v.z, q1v.w};
#pragma unroll
        for (int j = 0; j < 4; ++j) {
            const float* lrow = lamc_sm + (kk0 + j) * 64 + vg2 * 16;
            float4 l0 = ((const float4*)lrow)[0];
            float4 l1 = ((const float4*)lrow)[1];
            float4 l2 = ((const float4*)lrow)[2];
            float4 l3 = ((const float4*)lrow)[3];
            float lv[16] = {l0.x, l0.y, l0.z, l0.w, l1.x, l1.y, l1.z, l1.w,
                            l2.x, l2.y, l2.z, l2.w, l3.x, l3.y, l3.z, l3.w};
#pragma unroll
            for (int vi = 0; vi < 16; ++vi) {
                acc[0][vi] += q0a[j] * lv[vi];
                acc[1][vi] += q1a[j] * lv[vi];
            }
        }
    }

    // ---- Yp term: dy row-groups of the 7x7 stencil ----
    const int hs     = g & 3;                  // s-phase head
    const int ttlo   = (g >> 2) ? 4 : 0;       // tt range per half-group
    const int tthi   = (g >> 2) ? 7 : 4;

    for (int dy = 0; dy < RKS; ++dy) {
        __syncthreads();   // protect s_sm writers from previous-iteration readers
        {   // s phase: group computes s[hs][tt in range] for its pixel
            float4 qa = *(const float4*)(qrow + hs * 16 + 0);
            float4 qb4 = *(const float4*)(qrow + hs * 16 + 4);
            float4 qc = *(const float4*)(qrow + hs * 16 + 8);
            float4 qd = *(const float4*)(qrow + hs * 16 + 12);
            float qk[16] = {qa.x, qa.y, qa.z, qa.w, qb4.x, qb4.y, qb4.z, qb4.w,
                            qc.x, qc.y, qc.z, qc.w, qd.x, qd.y, qd.z, qd.w};
            for (int tt = ttlo; tt < tthi; ++tt) {
                float s = 0.f;
#pragma unroll
                for (int kk = 0; kk < 16; ++kk) s += qk[kk] * R_sm[kk * TAPS + dy * RKS + tt];
                srow[tt * 4 + hs] = s;
            }
        }
        __syncthreads();

#pragma unroll
        for (int dx = 0; dx < RKS; ++dx) {
            const int hp = (py + dy) * 14 + (px + dx);
            const float4* vp = (const float4*)(vh_sm + hp * VHPITCH + vg2 * 16);
            float4 v0 = vp[0], v1 = vp[1], v2 = vp[2], v3 = vp[3];
            float vv[16] = {v0.x, v0.y, v0.z, v0.w,
                            v1.x, v1.y, v1.z, v1.w,
                            v2.x, v2.y, v2.z, v2.w,
                            v3.x, v3.y, v3.z, v3.w};
            float2 s2 = *(const float2*)(srow + dx * 4 + 2 * hh);  // heads 2hh, 2hh+1
#pragma unroll
            for (int vi = 0; vi < 16; ++vi) {
                acc[0][vi] += s2.x * vv[vi];
                acc[1][vi] += s2.y * vv[vi];
            }
        }
    }

    // ---- store: out channel = (2hh+h)*64 + vg2*16 + vi ----
    const size_t ob = (size_t)b * 256 * NPIX;
    const int gp = (ty0 + py) * IMGW + tx0 + px;
#pragma unroll
    for (int h = 0; h < 2; ++h)
#pragma unroll
        for (int vi = 0; vi < 16; ++vi)
            out[ob + (size_t)((2 * hh + h) * 64 + vg2 * 16 + vi) * NPIX + gp] = acc[h][vi];
}

// ======================================================================
extern "C" void kernel_launch(void* const* d_in, const int* in_sizes, int n_in,
                              void* d_out, int out_size) {
    const float* x       = (const float*)d_in[0];
    const float* Wq      = (const float*)d_in[1];
    const float* Wk      = (const float*)d_in[2];
    const float* Wv      = (const float*)d_in[3];
    const float* gamma_q = (const float*)d_in[4];
    const float* beta_q  = (const float*)d_in[5];
    const float* gamma_v = (const float*)d_in[6];
    const float* beta_v  = (const float*)d_in[7];
    const float* R       = (const float*)d_in[8];
    float* out = (float*)d_out;

    const int smemK5 = (64 * QP + 196 * VHPITCH + 64 * SP + 1024 + 784) * (int)sizeof(float);
    cudaFuncSetAttribute(k_final, cudaFuncAttributeMaxDynamicSharedMemorySize, smemK5);

    k_proj<<<dim3(NPIX / 128, BATCH), 256>>>(x, Wq, Wk, Wv);
    k_bnstats<<<128, 256>>>(gamma_q, beta_q, gamma_v, beta_v);
    k_lamc<<<BATCH * 16, 256>>>();
    k_final<<<dim3(8, 8, BATCH), 512, smemK5>>>(R, out);
}

// round 6
// speedup vs baseline: 1.4580x; 1.0720x over previous
#include <cuda_runtime.h>
#include <math.h>

// ---------------- problem constants ----------------
#define BATCH   16
#define CIN     256
#define IMGH    64
#define IMGW    64
#define NPIX    4096          // 64*64
#define HEADS   4
#define DK      16
#define DV      64
#define RKS     7
#define TAPS    49            // 7*7
#define PADR    3

// ---------------- device scratch (globals: allowed) ----------------
__device__ float g_q[BATCH * 64 * NPIX];   // raw q projections [b][ch=h*16+k][p]
__device__ float g_k[BATCH * 16 * NPIX];   // raw k projections [b][k][p]
__device__ float g_v[BATCH * 64 * NPIX];   // raw v projections [b][v][p]
__device__ float g_sq[64], g_bq[64];       // BN fold for q: y = x*s + b
__device__ float g_sv[64], g_bv[64];       // BN fold for v
__device__ float g_lamc[BATCH * 16 * 64];  // lambda_c [b][k][v]

// ======================================================================
// K1: fused projection GEMM. Per batch: Y[144,4096] = W[144,256] * X[256,4096]
// ======================================================================
__global__ __launch_bounds__(256)
void k_proj(const float* __restrict__ x,
            const float* __restrict__ Wq,
            const float* __restrict__ Wk,
            const float* __restrict__ Wv) {
    __shared__ float Xs[16][128];
    __shared__ float Ws[144][17];

    const int b   = blockIdx.y;
    const int p0  = blockIdx.x * 128;
    const int tid = threadIdx.x;
    const int ty  = tid >> 4;
    const int tx  = tid & 15;

    const float* xb = x + (size_t)b * CIN * NPIX;

    float acc[9][8];
#pragma unroll
    for (int i = 0; i < 9; ++i)
#pragma unroll
        for (int j = 0; j < 8; ++j) acc[i][j] = 0.f;

    for (int c0 = 0; c0 < CIN; c0 += 16) {
#pragma unroll
        for (int r = 0; r < 8; ++r) {
            int idx = tid + r * 256;
            int cc  = idx >> 7;
            int pp  = idx & 127;
            Xs[cc][pp] = xb[(size_t)(c0 + cc) * NPIX + p0 + pp];
        }
#pragma unroll
        for (int r = 0; r < 9; ++r) {
            int idx = tid + r * 256;
            int o   = idx >> 4;
            int cc  = idx & 15;
            float w;
            if (o < 64)       w = Wq[o * CIN + c0 + cc];
            else if (o < 80)  w = Wk[(o - 64) * CIN + c0 + cc];
            else              w = Wv[(o - 80) * CIN + c0 + cc];
            Ws[o][cc] = w;
        }
        __syncthreads();

#pragma unroll
        for (int cc = 0; cc < 16; ++cc) {
            float a[9], bb[8];
#pragma unroll
            for (int i = 0; i < 9; ++i) a[i] = Ws[ty + 16 * i][cc];
#pragma unroll
            for (int j = 0; j < 8; ++j) bb[j] = Xs[cc][tx + 16 * j];
#pragma unroll
            for (int i = 0; i < 9; ++i)
#pragma unroll
                for (int j = 0; j < 8; ++j) acc[i][j] += a[i] * bb[j];
        }
        __syncthreads();
    }

#pragma unroll
    for (int i = 0; i < 9; ++i) {
        int o = ty + 16 * i;
        float* dst;
        if (o < 64)      dst = g_q + ((size_t)b * 64 + o) * NPIX;
        else if (o < 80) dst = g_k + ((size_t)b * 16 + (o - 64)) * NPIX;
        else             dst = g_v + ((size_t)b * 64 + (o - 80)) * NPIX;
#pragma unroll
        for (int j = 0; j < 8; ++j) dst[p0 + tx + 16 * j] = acc[i][j];
    }
}

// ======================================================================
// K2: BN statistics -> folded scale/bias. 128 blocks.
// ======================================================================
__global__ __launch_bounds__(256)
void k_bnstats(const float* __restrict__ gamma_q, const float* __restrict__ beta_q,
               const float* __restrict__ gamma_v, const float* __restrict__ beta_v) {
    const int ch  = blockIdx.x;
    const int tid = threadIdx.x;

    const float* src;
    float gamma, beta;
    float *sdst, *bdst;
    if (ch < 64) {
        src = g_q + (size_t)ch * NPIX;
        gamma = gamma_q[ch]; beta = beta_q[ch];
        sdst = &g_sq[ch]; bdst = &g_bq[ch];
    } else {
        int c = ch - 64;
        src = g_v + (size_t)c * NPIX;
        gamma = gamma_v[c]; beta = beta_v[c];
        sdst = &g_sv[c]; bdst = &g_bv[c];
    }

    float s = 0.f, s2 = 0.f;
    for (int b = 0; b < BATCH; ++b) {
        const float* p = src + (size_t)b * 64 * NPIX;
        for (int i = tid; i < NPIX; i += 256) {
            float v = p[i];
            s  += v;
            s2 += v * v;
        }
    }
    __shared__ float ss[256], ss2[256];
    ss[tid] = s; ss2[tid] = s2;
    __syncthreads();
    for (int st = 128; st > 0; st >>= 1) {
        if (tid < st) { ss[tid] += ss[tid + st]; ss2[tid] += ss2[tid + st]; }
        __syncthreads();
    }
    if (tid == 0) {
        const float inv_n = 1.0f / 65536.0f;
        float mean = ss[0] * inv_n;
        float var  = ss2[0] * inv_n - mean * mean;
        float sc   = gamma * rsqrtf(var + 1e-5f);
        *sdst = sc;
        *bdst = beta - mean * sc;
    }
}

// ======================================================================
// K3: softmax over k row + lambda_c, fused. One block per (b, k).
// ======================================================================
__global__ __launch_bounds__(256)
void k_lamc() {
    const int bk  = blockIdx.x;
    const int b   = bk >> 4;
    const int kc  = bk & 15;
    const int tid = threadIdx.x;
    const int lane = tid & 31, wrp = tid >> 5;

    const float* krow = g_k + ((size_t)b * 16 + kc) * NPIX;
    const float* vb   = g_v + (size_t)b * 64 * NPIX;

    __shared__ float red[256];

    float m = -1e30f;
    for (int i = tid; i < NPIX; i += 256) m = fmaxf(m, krow[i]);
    red[tid] = m;
    __syncthreads();
    for (int st = 128; st > 0; st >>= 1) {
        if (tid < st) red[tid] = fmaxf(red[tid], red[tid + st]);
        __syncthreads();
    }
    m = red[0];
    __syncthreads();

    float acc[64];
#pragma unroll
    for (int v = 0; v < 64; ++v) acc[v] = 0.f;
    float z = 0.f;

    for (int i = tid; i < NPIX; i += 256) {
        float w = expf(krow[i] - m);
        z += w;
#pragma unroll
        for (int v = 0; v < 64; ++v) acc[v] += w * vb[(size_t)v * NPIX + i];
    }

    red[tid] = z;
    __syncthreads();
    for (int st = 128; st > 0; st >>= 1) {
        if (tid < st) red[tid] += red[tid + st];
        __syncthreads();
    }
    z = red[0];
    __syncthreads();
    const float invz = 1.0f / z;

    __shared__ float part[64][8];
#pragma unroll
    for (int v = 0; v < 64; ++v) {
        float xv = acc[v];
#pragma unroll
        for (int o = 16; o > 0; o >>= 1) xv += __shfl_down_sync(0xffffffffu, xv, o);
        if (lane == 0) part[v][wrp] = xv;
    }
    __syncthreads();
    if (tid < 64) {
        float sum = 0.f;
#pragma unroll
        for (int i = 0; i < 8; ++i) sum += part[tid][i];
        g_lamc[((size_t)b * 16 + kc) * 64 + tid] = g_sv[tid] * sum * invz + g_bv[tid];
    }
}

// ======================================================================
// K5: final fused output. 512 threads = 64 pix x 8 v-groups (8 v each).
// Each thread: ALL 4 heads x 8 v channels -> v loads amortized over 4 heads.
// Per tap: 2x LDS.128 (v) + 1x LDS.128 (s, 4 heads) for 32 FMAs = 1.5 B/FMA.
// acc[4][8] = 32 regs. launch_bounds(512,2) -> 32 warps/SM.
// s-phase: group g computes head g&3, tt-range (g>>2 ? 4..6 : 0..3).
// ======================================================================
#define VHPITCH 68
#define QP      68
#define SP      28   // s pitch per pixel: 7 tt * 4 heads

__global__ __launch_bounds__(512, 2)
void k_final(const float* __restrict__ R, float* __restrict__ out) {
    extern __shared__ float sm[];
    float* q_sm    = sm;                     // [64 pix][QP]             4352
    float* vh_sm   = q_sm + 64 * QP;         // [196 hpix][VHPITCH]     13328
    float* s_sm    = vh_sm + 196 * VHPITCH;  // [64 pix][SP]             1792
    float* lamc_sm = s_sm + 64 * SP;         // [16 k][64 v]             1024
    float* R_sm    = lamc_sm + 1024;         // [16 k][49 t]              784

    const int b   = blockIdx.z;
    const int tx0 = blockIdx.x * 8;
    const int ty0 = blockIdx.y * 8;
    const int tid = threadIdx.x;

    // ---- loads (512 threads) ----
    for (int i = tid; i < 784; i += 512)  R_sm[i]    = R[i];
    for (int i = tid; i < 1024; i += 512) lamc_sm[i] = g_lamc[(size_t)b * 1024 + i];

    {   // q tile with BN, transposed [pix][ch]
        const float* qb = g_q + (size_t)b * 64 * NPIX;
        for (int idx = tid; idx < 4096; idx += 512) {
            int ch = idx >> 6, lp = idx & 63;
            int ly = lp >> 3,  lx = lp & 7;
            float v = qb[(size_t)ch * NPIX + (ty0 + ly) * IMGW + tx0 + lx];
            q_sm[lp * QP + ch] = v * g_sq[ch] + g_bq[ch];
        }
    }
    {   // v halo 14x14 with BN + zero pad, [hpix][ch]
        const float* vb = g_v + (size_t)b * 64 * NPIX;
        for (int idx = tid; idx < 196 * 64; idx += 512) {
            int ch = idx / 196, hp = idx - ch * 196;
            int hy = hp / 14,   hx = hp - hy * 14;
            int gy = ty0 + hy - PADR, gx = tx0 + hx - PADR;
            float v = 0.f;
            if (gy >= 0 && gy < IMGH && gx >= 0 && gx < IMGW)
                v = vb[(size_t)ch * NPIX + gy * IMGW + gx] * g_sv[ch] + g_bv[ch];
            vh_sm[hp * VHPITCH + ch] = v;
        }
    }
    __syncthreads();

    const int g   = tid >> 6;        // group 0..7 : v channels g*8..g*8+7
    const int pix = tid & 63;
    const int py  = pix >> 3, px = pix & 7;
    const float* qrow = q_sm + pix * QP;
    float* srow = s_sm + pix * SP;

    float acc[4][8];
#pragma unroll
    for (int h = 0; h < 4; ++h)
#pragma unroll
        for (int vi = 0; vi < 8; ++vi) acc[h][vi] = 0.f;

    // ---- Yc term (all 4 heads, 8 v channels) ----
#pragma unroll
    for (int kk0 = 0; kk0 < 16; kk0 += 4) {
        float4 qh[4];
#pragma unroll
        for (int h = 0; h < 4; ++h)
            qh[h] = *(const float4*)(qrow + h * 16 + kk0);
#pragma unroll
        for (int j = 0; j < 4; ++j) {
            const float* lrow = lamc_sm + (kk0 + j) * 64 + g * 8;
            float4 l0 = ((const float4*)lrow)[0];
            float4 l1 = ((const float4*)lrow)[1];
            float lv[8] = {l0.x, l0.y, l0.z, l0.w, l1.x, l1.y, l1.z, l1.w};
            float q0 = (j == 0) ? qh[0].x : (j == 1) ? qh[0].y : (j == 2) ? qh[0].z : qh[0].w;
            float q1 = (j == 0) ? qh[1].x : (j == 1) ? qh[1].y : (j == 2) ? qh[1].z : qh[1].w;
            float q2 = (j == 0) ? qh[2].x : (j == 1) ? qh[2].y : (j == 2) ? qh[2].z : qh[2].w;
            float q3 = (j == 0) ? qh[3].x : (j == 1) ? qh[3].y : (j == 2) ? qh[3].z : qh[3].w;
#pragma unroll
            for (int vi = 0; vi < 8; ++vi) {
                acc[0][vi] += q0 * lv[vi];
                acc[1][vi] += q1 * lv[vi];
                acc[2][vi] += q2 * lv[vi];
                acc[3][vi] += q3 * lv[vi];
            }
        }
    }

    // ---- Yp term: dy row-groups of the 7x7 stencil ----
    const int hs   = g & 3;                  // s-phase head
    const int ttlo = (g >> 2) ? 4 : 0;       // tt range per half-group
    const int tthi = (g >> 2) ? 7 : 4;

    for (int dy = 0; dy < RKS; ++dy) {
        __syncthreads();   // protect s_sm writers from previous-iteration readers
        {   // s phase
            float4 qa  = *(const float4*)(qrow + hs * 16 + 0);
            float4 qb4 = *(const float4*)(qrow + hs * 16 + 4);
            float4 qc  = *(const float4*)(qrow + hs * 16 + 8);
            float4 qd  = *(const float4*)(qrow + hs * 16 + 12);
            float qk[16] = {qa.x, qa.y, qa.z, qa.w, qb4.x, qb4.y, qb4.z, qb4.w,
                            qc.x, qc.y, qc.z, qc.w, qd.x, qd.y, qd.z, qd.w};
            for (int tt = ttlo; tt < tthi; ++tt) {
                float s = 0.f;
#pragma unroll
                for (int kk = 0; kk < 16; ++kk) s += qk[kk] * R_sm[kk * TAPS + dy * RKS + tt];
                srow[tt * 4 + hs] = s;
            }
        }
        __syncthreads();

#pragma unroll
        for (int dx = 0; dx < RKS; ++dx) {
            const int hp = (py + dy) * 14 + (px + dx);
            const float4* vp = (const float4*)(vh_sm + hp * VHPITCH + g * 8);
            float4 v0 = vp[0], v1 = vp[1];
            float vv[8] = {v0.x, v0.y, v0.z, v0.w, v1.x, v1.y, v1.z, v1.w};
            float4 s4 = *(const float4*)(srow + dx * 4);   // heads 0..3
#pragma unroll
            for (int vi = 0; vi < 8; ++vi) {
                acc[0][vi] += s4.x * vv[vi];
                acc[1][vi] += s4.y * vv[vi];
                acc[2][vi] += s4.z * vv[vi];
                acc[3][vi] += s4.w * vv[vi];
            }
        }
    }

    // ---- store: out channel = h*64 + g*8 + vi ----
    const size_t ob = (size_t)b * 256 * NPIX;
    const int gp = (ty0 + py) * IMGW + tx0 + px;
#pragma unroll
    for (int h = 0; h < 4; ++h)
#pragma unroll
        for (int vi = 0; vi < 8; ++vi)
            out[ob + (size_t)(h * 64 + g * 8 + vi) * NPIX + gp] = acc[h][vi];
}

// ======================================================================
extern "C" void kernel_launch(void* const* d_in, const int* in_sizes, int n_in,
                              void* d_out, int out_size) {
    const float* x       = (const float*)d_in[0];
    const float* Wq      = (const float*)d_in[1];
    const float* Wk      = (const float*)d_in[2];
    const float* Wv      = (const float*)d_in[3];
    const float* gamma_q = (const float*)d_in[4];
    const float* beta_q  = (const float*)d_in[5];
    const float* gamma_v = (const float*)d_in[6];
    const float* beta_v  = (const float*)d_in[7];
    const float* R       = (const float*)d_in[8];
    float* out = (float*)d_out;

    const int smemK5 = (64 * QP + 196 * VHPITCH + 64 * SP + 1024 + 784) * (int)sizeof(float);
    cudaFuncSetAttribute(k_final, cudaFuncAttributeMaxDynamicSharedMemorySize, smemK5);

    k_proj<<<dim3(NPIX / 128, BATCH), 256>>>(x, Wq, Wk, Wv);
    k_bnstats<<<128, 256>>>(gamma_q, beta_q, gamma_v, beta_v);
    k_lamc<<<BATCH * 16, 256>>>();
    k_final<<<dim3(8, 8, BATCH), 512, smemK5>>>(R, out);
}